// round 7
// baseline (speedup 1.0000x reference)
#include <cuda_runtime.h>
#include <cuda_bf16.h>
#include <math.h>
#include <stdint.h>

#define N_NODES 65536
#define N_EDGES 524288
#define C 128
#define L 3
#define BN_EPS 1e-5f

// ---------------- scratch (device globals; no dynamic allocation) ----------------
__device__ float  g_h[N_NODES * C];       // layer output (input for next layer)
__device__ float  g_neigh[N_NODES * C];   // aggregated raw neighbor features (already /deg)
__device__ float  g_wbar[N_NODES];        // (sum of edge weights)/deg per node
__device__ float2 g_edge[N_EDGES];        // CSR-by-dst packed records: (src bits, log1p(w))
__device__ int    g_degcnt[N_NODES];
__device__ int    g_off[N_NODES + 1];
__device__ int    g_cursor[N_NODES];
__device__ float  g_deginv[N_NODES];
__device__ float  g_stats[L * 2 * C];     // per-layer [sum(C) | sumsq(C)]
// pre-packed bf16 weight fragments in mma.sync per-lane order:
// [l][chunk][hilo][kstep(8)][nt16(16)][lane(32)] -> uint2 {b0, b1}
#define BPK_PER_CHUNK 8192
__device__ __align__(16) uint2 g_Bpk[L * 2 * BPK_PER_CHUNK];

// ---------------- helpers ----------------
__device__ __forceinline__ uint32_t pack_bf16x2(float lo, float hi) {
    uint32_t r;
    asm("cvt.rn.bf16x2.f32 %0, %1, %2;" : "=r"(r) : "f"(hi), "f"(lo));
    return r;
}
__device__ __forceinline__ void cvt_hilo(float2 v, uint32_t& hi, uint32_t& lo) {
    hi = pack_bf16x2(v.x, v.y);
    float f0 = __uint_as_float(hi << 16);
    float f1 = __uint_as_float(hi & 0xFFFF0000u);
    lo = pack_bf16x2(v.x - f0, v.y - f1);
}
__device__ __forceinline__ void mma_bf16(float* d, const uint32_t* a, uint32_t b0, uint32_t b1) {
    asm volatile(
        "mma.sync.aligned.m16n8k16.row.col.f32.bf16.bf16.f32 "
        "{%0,%1,%2,%3}, {%4,%5,%6,%7}, {%8,%9}, {%0,%1,%2,%3};"
        : "+f"(d[0]), "+f"(d[1]), "+f"(d[2]), "+f"(d[3])
        : "r"(a[0]), "r"(a[1]), "r"(a[2]), "r"(a[3]), "r"(b0), "r"(b1));
}

// ---------------- prep ----------------
__global__ void k_prep0() {
    int i = blockIdx.x * blockDim.x + threadIdx.x;
    if (i < N_NODES) g_degcnt[i] = 0;
    if (i < L * 2 * C) g_stats[i] = 0.0f;
}
__global__ void k_count(const int* __restrict__ dst) {
    int e = blockIdx.x * blockDim.x + threadIdx.x;
    if (e < N_EDGES) atomicAdd(&g_degcnt[dst[e]], 1);
}
__global__ void k_scan() {
    __shared__ int sp[1024];
    int t = threadIdx.x;
    int base = t * 64;
    int sum = 0;
    #pragma unroll 4
    for (int i = 0; i < 64; i++) sum += g_degcnt[base + i];
    sp[t] = sum;
    __syncthreads();
    for (int o = 1; o < 1024; o <<= 1) {
        int v = (t >= o) ? sp[t - o] : 0;
        __syncthreads();
        sp[t] += v;
        __syncthreads();
    }
    int run = sp[t] - sum;
    for (int i = 0; i < 64; i++) {
        int cnt = g_degcnt[base + i];
        g_off[base + i] = run;
        g_cursor[base + i] = run;
        g_deginv[base + i] = 1.0f / fmaxf((float)cnt, 1.0f);
        run += cnt;
    }
    if (t == 1023) g_off[N_NODES] = run;
}
__global__ void k_scatter(const int* __restrict__ src, const int* __restrict__ dst,
                          const float* __restrict__ ew) {
    int e = blockIdx.x * blockDim.x + threadIdx.x;
    if (e >= N_EDGES) return;
    int p = atomicAdd(&g_cursor[dst[e]], 1);
    g_edge[p] = make_float2(__int_as_float(src[e]), log1pf(ew[e]));
}

// ---------------- prep: weights -> pre-packed bf16 hi/lo mma fragments ----------------
__global__ void k_wprep(const float* __restrict__ Ws, const float* __restrict__ Wn) {
    int i = blockIdx.x * blockDim.x + threadIdx.x;
    if (i >= L * 2 * BPK_PER_CHUNK) return;
    int lane  = i & 31;
    int nt    = (i >> 5) & 15;
    int kstep = (i >> 9) & 7;
    int hilo  = (i >> 12) & 1;
    int chunk = (i >> 13) & 1;
    int l     = i >> 14;
    const float* W = (chunk ? Wn : Ws) + (size_t)l * 16384;
    int k0 = kstep * 16 + (lane & 3) * 2;
    int n  = nt * 8 + (lane >> 2);
    float v0 = W[(k0 + 0) * 128 + n], v1 = W[(k0 + 1) * 128 + n];
    float v2 = W[(k0 + 8) * 128 + n], v3 = W[(k0 + 9) * 128 + n];
    uint32_t h0, l0, h1, l1;
    cvt_hilo(make_float2(v0, v1), h0, l0);
    cvt_hilo(make_float2(v2, v3), h1, l1);
    g_Bpk[i] = hilo ? make_uint2(l0, l1) : make_uint2(h0, h1);
}

// ---------------- one-time: BN column stats of x (layer 0) ----------------
__global__ void k_stats(const float* __restrict__ x) {
    int tid = threadIdx.x;
    int c = tid & (C - 1);
    int rr = tid >> 7;
    float s = 0.0f, s2 = 0.0f;
    for (int r = blockIdx.x * 2 + rr; r < N_NODES; r += gridDim.x * 2) {
        float v = x[(size_t)r * C + c];
        s += v; s2 += v * v;
    }
    atomicAdd(&g_stats[c], s);
    atomicAdd(&g_stats[C + c], s2);
}

// ---------------- per-layer: raw mean aggregation + wbar, predicated 4-wide ---------
__global__ void k_aggr(const float* __restrict__ in) {
    int n = (blockIdx.x * blockDim.x + threadIdx.x) >> 5;
    int lane = threadIdx.x & 31;
    if (n >= N_NODES) return;
    int beg = g_off[n], end = g_off[n + 1];
    const float4* in4 = (const float4*)in;
    float4 a0 = make_float4(0.f, 0.f, 0.f, 0.f);
    float4 a1 = make_float4(0.f, 0.f, 0.f, 0.f);
    float ws = 0.f;
    int il = end - 1;
    for (int base = beg; base < end; base += 4) {
        float2 e0 = g_edge[base];
        float2 e1 = g_edge[min(base + 1, il)];
        float2 e2 = g_edge[min(base + 2, il)];
        float2 e3 = g_edge[min(base + 3, il)];
        float w0 = e0.y;
        float w1 = (base + 1 < end) ? e1.y : 0.f;
        float w2 = (base + 2 < end) ? e2.y : 0.f;
        float w3 = (base + 3 < end) ? e3.y : 0.f;
        float4 v0 = __ldg(&in4[(size_t)__float_as_int(e0.x) * 32 + lane]);
        float4 v1 = __ldg(&in4[(size_t)__float_as_int(e1.x) * 32 + lane]);
        float4 v2 = __ldg(&in4[(size_t)__float_as_int(e2.x) * 32 + lane]);
        float4 v3 = __ldg(&in4[(size_t)__float_as_int(e3.x) * 32 + lane]);
        a0.x += w0 * v0.x; a0.y += w0 * v0.y; a0.z += w0 * v0.z; a0.w += w0 * v0.w;
        a1.x += w1 * v1.x; a1.y += w1 * v1.y; a1.z += w1 * v1.z; a1.w += w1 * v1.w;
        a0.x += w2 * v2.x; a0.y += w2 * v2.y; a0.z += w2 * v2.z; a0.w += w2 * v2.w;
        a1.x += w3 * v3.x; a1.y += w3 * v3.y; a1.z += w3 * v3.z; a1.w += w3 * v3.w;
        ws += (w0 + w1) + (w2 + w3);
    }
    float di = g_deginv[n];
    float4 acc = make_float4((a0.x + a1.x) * di, (a0.y + a1.y) * di,
                             (a0.z + a1.z) * di, (a0.w + a1.w) * di);
    ((float4*)g_neigh)[(size_t)n * 32 + lane] = acc;
    if (lane == 0) g_wbar[n] = ws * di;
}

// ---------------- per-layer: mma.sync dual GEMM, fused BN coef+affine+stats/dot -----
// Prologue computes scale/shift from g_stats (replaces k_coef).
// A0 = sc*in + sh; A1 = sc*neigh + sh*wbar. D = A0@Ws + A1@Wn + bias, ReLU.
// mode 0: write g_h + accumulate next-layer BN stats.
// mode 1 (last layer): fused final dot -> out[n] = row . lin_w + lin_b (no g_h write).
// smem: 131072 (both B chunk images) + 512 + 512 + 1024 = 133120
#define GEMM_SMEM (131072 + 2048)

__global__ __launch_bounds__(256)
void k_gemm(int l, const float* __restrict__ Ain,
            const float* __restrict__ gamma, const float* __restrict__ beta,
            const float* __restrict__ bias,
            const float* __restrict__ lin_w, const float* __restrict__ lin_b,
            float* __restrict__ out, int mode) {
    extern __shared__ unsigned char dyn[];
    uint2* sB    = (uint2*)dyn;                 // [2][8192] packed B fragments
    float* sSc   = (float*)(dyn + 131072);      // 128
    float* sSh   = sSc + 128;                   // 128
    float* sStat = sSh + 128;                   // 256 (stats accum / dot reduction)

    int tid = threadIdx.x, wid = tid >> 5, lane = tid & 31;
    int wm = wid >> 1, wn = wid & 1;
    int row0 = blockIdx.x * 128;

    // BN affine coefficients (replaces k_coef kernel)
    if (tid < 128) {
        float sum = g_stats[l * 2 * C + tid];
        float sq  = g_stats[l * 2 * C + C + tid];
        float mu  = sum * (1.0f / N_NODES);
        float var = sq * (1.0f / N_NODES) - mu * mu;
        float sc  = gamma[l * C + tid] * rsqrtf(var + BN_EPS);
        sSc[tid] = sc;
        sSh[tid] = beta[l * C + tid] - mu * sc;
    }
    if (tid < 256) sStat[tid] = 0.0f;
    // copy both chunk B images (128KB)
    {
        const uint4* src = (const uint4*)(g_Bpk + (size_t)(l * 2) * BPK_PER_CHUNK);
        uint4* dst = (uint4*)sB;
        #pragma unroll
        for (int it = 0; it < 32; it++) dst[it * 256 + tid] = src[it * 256 + tid];
    }
    __syncthreads();

    float acc[2][8][4];
    #pragma unroll
    for (int mt = 0; mt < 2; mt++)
        #pragma unroll
        for (int nt = 0; nt < 8; nt++)
            #pragma unroll
            for (int q = 0; q < 4; q++) acc[mt][nt][q] = 0.0f;

    int ar = row0 + wm * 32 + (lane >> 2);
    int ak = (lane & 3) * 2;
    float wbr[4] = { g_wbar[ar], g_wbar[ar + 8], g_wbar[ar + 16], g_wbar[ar + 24] };

    #pragma unroll 1
    for (int chunk = 0; chunk < 2; chunk++) {
        const float* Asrc = chunk ? g_neigh : Ain;
        const uint2* sBc = sB + chunk * 8192;
        float mm[4];
        #pragma unroll
        for (int j = 0; j < 4; j++) mm[j] = chunk ? wbr[j] : 1.0f;

        // register double-buffered A loads: buf layout
        // j: 0:(r+0,k) 1:(r+8,k) 2:(r+0,k+8) 3:(r+8,k+8) 4..7 same with +16 rows
        float2 abuf0[8], abuf1[8];
        {
            const float* p = Asrc + (size_t)ar * C + ak;
            abuf0[0] = *(const float2*)(p);
            abuf0[1] = *(const float2*)(p + 8 * C);
            abuf0[2] = *(const float2*)(p + 8);
            abuf0[3] = *(const float2*)(p + 8 * C + 8);
            abuf0[4] = *(const float2*)(p + 16 * C);
            abuf0[5] = *(const float2*)(p + 24 * C);
            abuf0[6] = *(const float2*)(p + 16 * C + 8);
            abuf0[7] = *(const float2*)(p + 24 * C + 8);
        }
        #pragma unroll 2
        for (int ks = 0; ks < 8; ks++) {
            float2* cur = (ks & 1) ? abuf1 : abuf0;
            float2* nxt = (ks & 1) ? abuf0 : abuf1;
            if (ks < 7) {
                const float* p = Asrc + (size_t)ar * C + (ks + 1) * 16 + ak;
                nxt[0] = *(const float2*)(p);
                nxt[1] = *(const float2*)(p + 8 * C);
                nxt[2] = *(const float2*)(p + 8);
                nxt[3] = *(const float2*)(p + 8 * C + 8);
                nxt[4] = *(const float2*)(p + 16 * C);
                nxt[5] = *(const float2*)(p + 24 * C);
                nxt[6] = *(const float2*)(p + 16 * C + 8);
                nxt[7] = *(const float2*)(p + 24 * C + 8);
            }
            int kk = ks * 16 + ak;
            float2 scA = *(const float2*)&sSc[kk];
            float2 scB = *(const float2*)&sSc[kk + 8];
            float2 shA = *(const float2*)&sSh[kk];
            float2 shB = *(const float2*)&sSh[kk + 8];

            uint32_t ahi[2][4], alo[2][4];
            #pragma unroll
            for (int mt = 0; mt < 2; mt++) {
                float m0 = mm[2 * mt], m1 = mm[2 * mt + 1];
                float2 v;
                v = cur[mt * 4 + 0];
                v.x = v.x * scA.x + shA.x * m0; v.y = v.y * scA.y + shA.y * m0;
                cvt_hilo(v, ahi[mt][0], alo[mt][0]);
                v = cur[mt * 4 + 1];
                v.x = v.x * scA.x + shA.x * m1; v.y = v.y * scA.y + shA.y * m1;
                cvt_hilo(v, ahi[mt][1], alo[mt][1]);
                v = cur[mt * 4 + 2];
                v.x = v.x * scB.x + shB.x * m0; v.y = v.y * scB.y + shB.y * m0;
                cvt_hilo(v, ahi[mt][2], alo[mt][2]);
                v = cur[mt * 4 + 3];
                v.x = v.x * scB.x + shB.x * m1; v.y = v.y * scB.y + shB.y * m1;
                cvt_hilo(v, ahi[mt][3], alo[mt][3]);
            }
            #pragma unroll
            for (int nt = 0; nt < 8; nt++) {
                int ntg = wn * 8 + nt;
                uint2 bhi = sBc[(ks * 16 + ntg) * 32 + lane];
                uint2 blo = sBc[4096 + (ks * 16 + ntg) * 32 + lane];
                #pragma unroll
                for (int mt = 0; mt < 2; mt++) {
                    mma_bf16(acc[mt][nt], ahi[mt], bhi.x, bhi.y);
                    mma_bf16(acc[mt][nt], ahi[mt], blo.x, blo.y);
                    mma_bf16(acc[mt][nt], alo[mt], bhi.x, bhi.y);
                }
            }
        }
    }

    if (mode == 0) {
        // epilogue: bias + ReLU, write g_h, accumulate next-layer BN stats
        #pragma unroll
        for (int nt = 0; nt < 8; nt++) {
            int col = wn * 64 + nt * 8 + (lane & 3) * 2;
            float b0 = bias[col], b1 = bias[col + 1];
            float s0 = 0.f, s1 = 0.f, q0 = 0.f, q1 = 0.f;
            #pragma unroll
            for (int mt = 0; mt < 2; mt++) {
                int r = ar + mt * 16;
                float o00 = fmaxf(acc[mt][nt][0] + b0, 0.f);
                float o01 = fmaxf(acc[mt][nt][1] + b1, 0.f);
                float o10 = fmaxf(acc[mt][nt][2] + b0, 0.f);
                float o11 = fmaxf(acc[mt][nt][3] + b1, 0.f);
                *(float2*)(g_h + (size_t)r * C + col)       = make_float2(o00, o01);
                *(float2*)(g_h + (size_t)(r + 8) * C + col) = make_float2(o10, o11);
                s0 += o00 + o10; s1 += o01 + o11;
                q0 += o00 * o00 + o10 * o10; q1 += o01 * o01 + o11 * o11;
            }
            #pragma unroll
            for (int off = 16; off >= 4; off >>= 1) {
                s0 += __shfl_down_sync(0xffffffffu, s0, off);
                s1 += __shfl_down_sync(0xffffffffu, s1, off);
                q0 += __shfl_down_sync(0xffffffffu, q0, off);
                q1 += __shfl_down_sync(0xffffffffu, q1, off);
            }
            if (lane < 4) {
                atomicAdd(&sStat[col],           s0);
                atomicAdd(&sStat[col + 1],       s1);
                atomicAdd(&sStat[128 + col],     q0);
                atomicAdd(&sStat[128 + col + 1], q1);
            }
        }
        __syncthreads();
        if (tid < 128) {
            atomicAdd(&g_stats[(l + 1) * 2 * C + tid],     sStat[tid]);
            atomicAdd(&g_stats[(l + 1) * 2 * C + C + tid], sStat[128 + tid]);
        }
    } else {
        // last layer: fused final dot. p[j] = partial over this thread's cols for
        // rows ar+{0,8,16,24}
        float p[4] = {0.f, 0.f, 0.f, 0.f};
        #pragma unroll
        for (int nt = 0; nt < 8; nt++) {
            int col = wn * 64 + nt * 8 + (lane & 3) * 2;
            float b0 = bias[col], b1 = bias[col + 1];
            float lw0 = lin_w[col], lw1 = lin_w[col + 1];
            #pragma unroll
            for (int mt = 0; mt < 2; mt++) {
                float o00 = fmaxf(acc[mt][nt][0] + b0, 0.f);
                float o01 = fmaxf(acc[mt][nt][1] + b1, 0.f);
                float o10 = fmaxf(acc[mt][nt][2] + b0, 0.f);
                float o11 = fmaxf(acc[mt][nt][3] + b1, 0.f);
                p[2 * mt]     += o00 * lw0 + o01 * lw1;
                p[2 * mt + 1] += o10 * lw0 + o11 * lw1;
            }
        }
        #pragma unroll
        for (int j = 0; j < 4; j++) {
            p[j] += __shfl_xor_sync(0xffffffffu, p[j], 1);
            p[j] += __shfl_xor_sync(0xffffffffu, p[j], 2);
        }
        if ((lane & 3) == 0) {
            int rloc = wm * 32 + (lane >> 2);
            sStat[(rloc + 0)  * 2 + wn] = p[0];
            sStat[(rloc + 8)  * 2 + wn] = p[1];
            sStat[(rloc + 16) * 2 + wn] = p[2];
            sStat[(rloc + 24) * 2 + wn] = p[3];
        }
        __syncthreads();
        if (tid < 128)
            out[row0 + tid] = sStat[tid * 2] + sStat[tid * 2 + 1] + lin_b[0];
    }
}

// ---------------- launch ----------------
extern "C" void kernel_launch(void* const* d_in, const int* in_sizes, int n_in,
                              void* d_out, int out_size) {
    const float* x      = (const float*)d_in[0];
    const float* ew     = (const float*)d_in[1];
    const float* gamma  = (const float*)d_in[2];
    const float* beta   = (const float*)d_in[3];
    const float* Wself  = (const float*)d_in[4];
    const float* Wneigh = (const float*)d_in[5];
    const float* bias   = (const float*)d_in[6];
    const float* lin_w  = (const float*)d_in[7];
    const float* lin_b  = (const float*)d_in[8];
    const int*   src    = (const int*)d_in[9];
    const int*   dst    = (const int*)d_in[10];
    float*       out    = (float*)d_out;

    (void)in_sizes; (void)n_in; (void)out_size;

    cudaFuncSetAttribute(k_gemm, cudaFuncAttributeMaxDynamicSharedMemorySize, GEMM_SMEM);

    float* hdev = nullptr;
    cudaGetSymbolAddress((void**)&hdev, g_h);

    k_prep0  <<<N_NODES / 256, 256>>>();
    k_count  <<<N_EDGES / 256, 256>>>(dst);
    k_scan   <<<1, 1024>>>();
    k_scatter<<<N_EDGES / 256, 256>>>(src, dst, ew);
    k_wprep  <<<(L * 2 * BPK_PER_CHUNK) / 256, 256>>>(Wself, Wneigh);
    k_stats  <<<256, 256>>>(x);

    for (int l = 0; l < L; l++) {
        const float* in = (l == 0) ? x : hdev;
        k_aggr<<<N_NODES * 32 / 256, 256>>>(in);
        k_gemm<<<N_NODES / 128, 256, GEMM_SMEM>>>(l, in, gamma, beta,
                                                  bias + (size_t)l * C,
                                                  lin_w, lin_b, out,
                                                  (l == L - 1) ? 1 : 0);
    }
}

// round 8
// speedup vs baseline: 1.0729x; 1.0729x over previous
#include <cuda_runtime.h>
#include <cuda_bf16.h>
#include <math.h>
#include <stdint.h>

#define N_NODES 65536
#define N_EDGES 524288
#define C 128
#define L 3
#define BN_EPS 1e-5f

// ---------------- scratch (device globals; no dynamic allocation) ----------------
__device__ float  g_h[N_NODES * C];       // layer output (input for next layer)
__device__ float  g_neigh[N_NODES * C];   // aggregated raw neighbor features (already /deg)
__device__ float  g_wbar[N_NODES];        // (sum of edge weights)/deg per node
__device__ float2 g_edge[N_EDGES];        // CSR-by-dst packed records: (src bits, log1p(w))
__device__ int    g_degcnt[N_NODES];
__device__ int    g_off[N_NODES + 1];
__device__ int    g_cursor[N_NODES];
__device__ float  g_deginv[N_NODES];
__device__ float  g_stats[L * 2 * C];     // per-layer [sum(C) | sumsq(C)]
// pre-packed bf16 weight fragments in mma.sync per-lane order:
// [l][chunk][hilo][kstep(8)][nt16(16)][lane(32)] -> uint2 {b0, b1}
#define BPK_PER_CHUNK 8192
__device__ __align__(16) uint2 g_Bpk[L * 2 * BPK_PER_CHUNK];

// ---------------- helpers ----------------
__device__ __forceinline__ uint32_t pack_bf16x2(float lo, float hi) {
    uint32_t r;
    asm("cvt.rn.bf16x2.f32 %0, %1, %2;" : "=r"(r) : "f"(hi), "f"(lo));
    return r;
}
__device__ __forceinline__ void cvt_hilo(float2 v, uint32_t& hi, uint32_t& lo) {
    hi = pack_bf16x2(v.x, v.y);
    float f0 = __uint_as_float(hi << 16);
    float f1 = __uint_as_float(hi & 0xFFFF0000u);
    lo = pack_bf16x2(v.x - f0, v.y - f1);
}
__device__ __forceinline__ void mma_bf16(float* d, const uint32_t* a, uint32_t b0, uint32_t b1) {
    asm volatile(
        "mma.sync.aligned.m16n8k16.row.col.f32.bf16.bf16.f32 "
        "{%0,%1,%2,%3}, {%4,%5,%6,%7}, {%8,%9}, {%0,%1,%2,%3};"
        : "+f"(d[0]), "+f"(d[1]), "+f"(d[2]), "+f"(d[3])
        : "r"(a[0]), "r"(a[1]), "r"(a[2]), "r"(a[3]), "r"(b0), "r"(b1));
}

// ---------------- prep ----------------
__global__ void k_prep0() {
    int i = blockIdx.x * blockDim.x + threadIdx.x;
    if (i < N_NODES) g_degcnt[i] = 0;
    if (i < L * 2 * C) g_stats[i] = 0.0f;
}
__global__ void k_count(const int* __restrict__ dst) {
    int e = blockIdx.x * blockDim.x + threadIdx.x;
    if (e < N_EDGES) atomicAdd(&g_degcnt[dst[e]], 1);
}
__global__ void k_scan() {
    __shared__ int sp[1024];
    int t = threadIdx.x;
    int base = t * 64;
    int sum = 0;
    #pragma unroll 4
    for (int i = 0; i < 64; i++) sum += g_degcnt[base + i];
    sp[t] = sum;
    __syncthreads();
    for (int o = 1; o < 1024; o <<= 1) {
        int v = (t >= o) ? sp[t - o] : 0;
        __syncthreads();
        sp[t] += v;
        __syncthreads();
    }
    int run = sp[t] - sum;
    for (int i = 0; i < 64; i++) {
        int cnt = g_degcnt[base + i];
        g_off[base + i] = run;
        g_cursor[base + i] = run;
        g_deginv[base + i] = 1.0f / fmaxf((float)cnt, 1.0f);
        run += cnt;
    }
    if (t == 1023) g_off[N_NODES] = run;
}
__global__ void k_scatter(const int* __restrict__ src, const int* __restrict__ dst,
                          const float* __restrict__ ew) {
    int e = blockIdx.x * blockDim.x + threadIdx.x;
    if (e >= N_EDGES) return;
    int p = atomicAdd(&g_cursor[dst[e]], 1);
    g_edge[p] = make_float2(__int_as_float(src[e]), log1pf(ew[e]));
}

// ---------------- prep: weights -> pre-packed bf16 hi/lo mma fragments ----------------
__global__ void k_wprep(const float* __restrict__ Ws, const float* __restrict__ Wn) {
    int i = blockIdx.x * blockDim.x + threadIdx.x;
    if (i >= L * 2 * BPK_PER_CHUNK) return;
    int lane  = i & 31;
    int nt    = (i >> 5) & 15;
    int kstep = (i >> 9) & 7;
    int hilo  = (i >> 12) & 1;
    int chunk = (i >> 13) & 1;
    int l     = i >> 14;
    const float* W = (chunk ? Wn : Ws) + (size_t)l * 16384;
    int k0 = kstep * 16 + (lane & 3) * 2;
    int n  = nt * 8 + (lane >> 2);
    float v0 = W[(k0 + 0) * 128 + n], v1 = W[(k0 + 1) * 128 + n];
    float v2 = W[(k0 + 8) * 128 + n], v3 = W[(k0 + 9) * 128 + n];
    uint32_t h0, l0, h1, l1;
    cvt_hilo(make_float2(v0, v1), h0, l0);
    cvt_hilo(make_float2(v2, v3), h1, l1);
    g_Bpk[i] = hilo ? make_uint2(l0, l1) : make_uint2(h0, h1);
}

// ---------------- one-time: BN column stats of x (layer 0) ----------------
__global__ void k_stats(const float* __restrict__ x) {
    int tid = threadIdx.x;
    int c = tid & (C - 1);
    int rr = tid >> 7;
    float s = 0.0f, s2 = 0.0f;
    for (int r = blockIdx.x * 2 + rr; r < N_NODES; r += gridDim.x * 2) {
        float v = x[(size_t)r * C + c];
        s += v; s2 += v * v;
    }
    atomicAdd(&g_stats[c], s);
    atomicAdd(&g_stats[C + c], s2);
}

// ---------------- per-layer: raw mean aggregation + wbar (R6-measured version) ------
__global__ void k_aggr(const float* __restrict__ in) {
    int n = (blockIdx.x * blockDim.x + threadIdx.x) >> 5;
    int lane = threadIdx.x & 31;
    if (n >= N_NODES) return;
    int beg = g_off[n], end = g_off[n + 1];
    const float4* in4 = (const float4*)in;
    float4 a0 = make_float4(0.f, 0.f, 0.f, 0.f);
    float4 a1 = make_float4(0.f, 0.f, 0.f, 0.f);
    float ws = 0.f;
    int i = beg;
    for (; i + 4 <= end; i += 4) {
        float2 e0 = g_edge[i],     e1 = g_edge[i + 1];
        float2 e2 = g_edge[i + 2], e3 = g_edge[i + 3];
        float4 v0 = __ldg(&in4[(size_t)__float_as_int(e0.x) * 32 + lane]);
        float4 v1 = __ldg(&in4[(size_t)__float_as_int(e1.x) * 32 + lane]);
        float4 v2 = __ldg(&in4[(size_t)__float_as_int(e2.x) * 32 + lane]);
        float4 v3 = __ldg(&in4[(size_t)__float_as_int(e3.x) * 32 + lane]);
        a0.x += e0.y * v0.x; a0.y += e0.y * v0.y; a0.z += e0.y * v0.z; a0.w += e0.y * v0.w;
        a1.x += e1.y * v1.x; a1.y += e1.y * v1.y; a1.z += e1.y * v1.z; a1.w += e1.y * v1.w;
        a0.x += e2.y * v2.x; a0.y += e2.y * v2.y; a0.z += e2.y * v2.z; a0.w += e2.y * v2.w;
        a1.x += e3.y * v3.x; a1.y += e3.y * v3.y; a1.z += e3.y * v3.z; a1.w += e3.y * v3.w;
        ws += (e0.y + e1.y) + (e2.y + e3.y);
    }
    for (; i < end; i++) {
        float2 e = g_edge[i];
        float4 v = __ldg(&in4[(size_t)__float_as_int(e.x) * 32 + lane]);
        a0.x += e.y * v.x; a0.y += e.y * v.y; a0.z += e.y * v.z; a0.w += e.y * v.w;
        ws += e.y;
    }
    float di = g_deginv[n];
    float4 acc = make_float4((a0.x + a1.x) * di, (a0.y + a1.y) * di,
                             (a0.z + a1.z) * di, (a0.w + a1.w) * di);
    ((float4*)g_neigh)[(size_t)n * 32 + lane] = acc;
    if (lane == 0) g_wbar[n] = ws * di;
}

// ---------------- per-layer: mma.sync dual GEMM, 8(M)x1(N) warps, fused BN ----------
// Warp w owns a 16-row x 128-col tile: every A element converted exactly once.
// A0 = sc*in + sh; A1 = sc*neigh + sh*wbar. D = A0@Ws + A1@Wn + bias, ReLU.
// mode 0: write g_h + accumulate next-layer BN stats.
// mode 1 (last layer): fused final dot -> out[n] = row . lin_w + lin_b.
// smem: 65536 (sB, one chunk staged at a time) + 512 + 512 + 1024 = 67584
#define GEMM_SMEM (65536 + 2048)

__global__ __launch_bounds__(256, 2)
void k_gemm(int l, const float* __restrict__ Ain,
            const float* __restrict__ gamma, const float* __restrict__ beta,
            const float* __restrict__ bias,
            const float* __restrict__ lin_w, const float* __restrict__ lin_b,
            float* __restrict__ out, int mode) {
    extern __shared__ unsigned char dyn[];
    uint2* sB    = (uint2*)dyn;                 // 64KB: packed B fragments (hi+lo)
    float* sSc   = (float*)(dyn + 65536);       // 128
    float* sSh   = sSc + 128;                   // 128
    float* sStat = sSh + 128;                   // 256

    int tid = threadIdx.x, wid = tid >> 5, lane = tid & 31;
    int row0 = blockIdx.x * 128;

    // BN affine coefficients (fused k_coef)
    if (tid < 128) {
        float sum = g_stats[l * 2 * C + tid];
        float sq  = g_stats[l * 2 * C + C + tid];
        float mu  = sum * (1.0f / N_NODES);
        float var = sq * (1.0f / N_NODES) - mu * mu;
        float sc  = gamma[l * C + tid] * rsqrtf(var + BN_EPS);
        sSc[tid] = sc;
        sSh[tid] = beta[l * C + tid] - mu * sc;
    }
    if (tid < 256) sStat[tid] = 0.0f;

    float acc[16][4];
    #pragma unroll
    for (int nt = 0; nt < 16; nt++)
        #pragma unroll
        for (int q = 0; q < 4; q++) acc[nt][q] = 0.0f;

    int ar = row0 + wid * 16 + (lane >> 2);   // A fragment base row (this + ar+8)
    int ak = (lane & 3) * 2;
    float wb0 = g_wbar[ar], wb1 = g_wbar[ar + 8];

    #pragma unroll 1
    for (int chunk = 0; chunk < 2; chunk++) {
        if (chunk) __syncthreads();
        {
            const uint4* src = (const uint4*)(g_Bpk + (size_t)(l * 2 + chunk) * BPK_PER_CHUNK);
            uint4* dst = (uint4*)sB;
            #pragma unroll
            for (int it = 0; it < 16; it++) dst[it * 256 + tid] = src[it * 256 + tid];
        }
        __syncthreads();

        const float* Asrc = chunk ? g_neigh : Ain;
        float m0 = chunk ? wb0 : 1.0f;
        float m1 = chunk ? wb1 : 1.0f;

        #pragma unroll 2
        for (int ks = 0; ks < 8; ks++) {
            int kk = ks * 16 + ak;
            float2 scA = *(const float2*)&sSc[kk];
            float2 scB = *(const float2*)&sSc[kk + 8];
            float2 shA = *(const float2*)&sSh[kk];
            float2 shB = *(const float2*)&sSh[kk + 8];

            const float* p = Asrc + (size_t)ar * C + kk;
            float2 v0 = *(const float2*)(p);
            float2 v1 = *(const float2*)(p + 8 * C);
            float2 v2 = *(const float2*)(p + 8);
            float2 v3 = *(const float2*)(p + 8 * C + 8);
            v0.x = v0.x * scA.x + shA.x * m0; v0.y = v0.y * scA.y + shA.y * m0;
            v1.x = v1.x * scA.x + shA.x * m1; v1.y = v1.y * scA.y + shA.y * m1;
            v2.x = v2.x * scB.x + shB.x * m0; v2.y = v2.y * scB.y + shB.y * m0;
            v3.x = v3.x * scB.x + shB.x * m1; v3.y = v3.y * scB.y + shB.y * m1;

            uint32_t ahi[4], alo[4];
            cvt_hilo(v0, ahi[0], alo[0]);
            cvt_hilo(v1, ahi[1], alo[1]);
            cvt_hilo(v2, ahi[2], alo[2]);
            cvt_hilo(v3, ahi[3], alo[3]);

            #pragma unroll
            for (int nt = 0; nt < 16; nt++) {
                uint2 bhi = sB[(ks * 16 + nt) * 32 + lane];
                uint2 blo = sB[4096 + (ks * 16 + nt) * 32 + lane];
                mma_bf16(acc[nt], ahi, bhi.x, bhi.y);
                mma_bf16(acc[nt], ahi, blo.x, blo.y);
                mma_bf16(acc[nt], alo, bhi.x, bhi.y);
            }
        }
    }

    if (mode == 0) {
        // epilogue: bias + ReLU, write g_h, accumulate next-layer BN stats
        #pragma unroll
        for (int nt = 0; nt < 16; nt++) {
            int col = nt * 8 + (lane & 3) * 2;
            float b0 = bias[col], b1 = bias[col + 1];
            float o00 = fmaxf(acc[nt][0] + b0, 0.f);
            float o01 = fmaxf(acc[nt][1] + b1, 0.f);
            float o10 = fmaxf(acc[nt][2] + b0, 0.f);
            float o11 = fmaxf(acc[nt][3] + b1, 0.f);
            *(float2*)(g_h + (size_t)ar * C + col)       = make_float2(o00, o01);
            *(float2*)(g_h + (size_t)(ar + 8) * C + col) = make_float2(o10, o11);
            float s0 = o00 + o10, s1 = o01 + o11;
            float q0 = o00 * o00 + o10 * o10, q1 = o01 * o01 + o11 * o11;
            #pragma unroll
            for (int off = 16; off >= 4; off >>= 1) {
                s0 += __shfl_down_sync(0xffffffffu, s0, off);
                s1 += __shfl_down_sync(0xffffffffu, s1, off);
                q0 += __shfl_down_sync(0xffffffffu, q0, off);
                q1 += __shfl_down_sync(0xffffffffu, q1, off);
            }
            if (lane < 4) {
                atomicAdd(&sStat[col],           s0);
                atomicAdd(&sStat[col + 1],       s1);
                atomicAdd(&sStat[128 + col],     q0);
                atomicAdd(&sStat[128 + col + 1], q1);
            }
        }
        __syncthreads();
        if (tid < 128) {
            atomicAdd(&g_stats[(l + 1) * 2 * C + tid],     sStat[tid]);
            atomicAdd(&g_stats[(l + 1) * 2 * C + C + tid], sStat[128 + tid]);
        }
    } else {
        // last layer: fused final dot over this warp's 16 rows
        float p0 = 0.f, p1 = 0.f;
        #pragma unroll
        for (int nt = 0; nt < 16; nt++) {
            int col = nt * 8 + (lane & 3) * 2;
            float b0 = bias[col], b1 = bias[col + 1];
            float lw0 = lin_w[col], lw1 = lin_w[col + 1];
            float o00 = fmaxf(acc[nt][0] + b0, 0.f);
            float o01 = fmaxf(acc[nt][1] + b1, 0.f);
            float o10 = fmaxf(acc[nt][2] + b0, 0.f);
            float o11 = fmaxf(acc[nt][3] + b1, 0.f);
            p0 += o00 * lw0 + o01 * lw1;
            p1 += o10 * lw0 + o11 * lw1;
        }
        p0 += __shfl_xor_sync(0xffffffffu, p0, 1);
        p0 += __shfl_xor_sync(0xffffffffu, p0, 2);
        p1 += __shfl_xor_sync(0xffffffffu, p1, 1);
        p1 += __shfl_xor_sync(0xffffffffu, p1, 2);
        if ((lane & 3) == 0) {
            float lb = lin_b[0];
            out[ar] = p0 + lb;
            out[ar + 8] = p1 + lb;
        }
    }
}

// ---------------- launch ----------------
extern "C" void kernel_launch(void* const* d_in, const int* in_sizes, int n_in,
                              void* d_out, int out_size) {
    const float* x      = (const float*)d_in[0];
    const float* ew     = (const float*)d_in[1];
    const float* gamma  = (const float*)d_in[2];
    const float* beta   = (const float*)d_in[3];
    const float* Wself  = (const float*)d_in[4];
    const float* Wneigh = (const float*)d_in[5];
    const float* bias   = (const float*)d_in[6];
    const float* lin_w  = (const float*)d_in[7];
    const float* lin_b  = (const float*)d_in[8];
    const int*   src    = (const int*)d_in[9];
    const int*   dst    = (const int*)d_in[10];
    float*       out    = (float*)d_out;

    (void)in_sizes; (void)n_in; (void)out_size;

    cudaFuncSetAttribute(k_gemm, cudaFuncAttributeMaxDynamicSharedMemorySize, GEMM_SMEM);

    float* hdev = nullptr;
    cudaGetSymbolAddress((void**)&hdev, g_h);

    k_prep0  <<<N_NODES / 256, 256>>>();
    k_count  <<<N_EDGES / 256, 256>>>(dst);
    k_scan   <<<1, 1024>>>();
    k_scatter<<<N_EDGES / 256, 256>>>(src, dst, ew);
    k_wprep  <<<(L * 2 * BPK_PER_CHUNK) / 256, 256>>>(Wself, Wneigh);
    k_stats  <<<256, 256>>>(x);

    for (int l = 0; l < L; l++) {
        const float* in = (l == 0) ? x : hdev;
        k_aggr<<<N_NODES * 32 / 256, 256>>>(in);
        k_gemm<<<N_NODES / 128, 256, GEMM_SMEM>>>(l, in, gamma, beta,
                                                  bias + (size_t)l * C,
                                                  lin_w, lin_b, out,
                                                  (l == L - 1) ? 1 : 0);
    }
}

// round 9
// speedup vs baseline: 1.1587x; 1.0799x over previous
#include <cuda_runtime.h>
#include <cuda_fp16.h>
#include <math.h>
#include <stdint.h>

#define N_NODES 65536
#define N_EDGES 524288
#define C 128
#define L 3
#define BN_EPS 1e-5f

// ---------------- scratch (device globals; no dynamic allocation) ----------------
__device__ float  g_h[N_NODES * C];       // layer output (input for next layer)
__device__ float  g_neigh[N_NODES * C];   // aggregated raw neighbor features (already /deg)
__device__ float  g_wbar[N_NODES];        // (sum of edge weights)/deg per node
__device__ float2 g_edge[N_EDGES];        // CSR-by-dst packed records: (src bits, log1p(w))
__device__ int    g_degcnt[N_NODES];
__device__ int    g_off[N_NODES + 1];
__device__ int    g_cursor[N_NODES];
__device__ float  g_deginv[N_NODES];
__device__ float  g_stats[L * 2 * C];     // per-layer [sum(C) | sumsq(C)]
// pre-packed fp16 weight fragments in mma.sync per-lane order (single precision pass):
// [l][chunk][kstep(8)][nt16(16)][lane(32)] -> uint2 {b0, b1} (f16x2 each)
#define BPK_PER_CHUNK 4096
__device__ __align__(16) uint2 g_Bpk[L * 2 * BPK_PER_CHUNK];

// ---------------- helpers ----------------
__device__ __forceinline__ uint32_t pack_f16x2(float2 v) {
    __half2 h = __float22half2_rn(v);
    return *(uint32_t*)&h;
}
// fp32 pair -> f16x2 hi + f16x2 residual (A split; exact to ~2^-24)
__device__ __forceinline__ void cvt_hilo_f16(float2 v, uint32_t& hi, uint32_t& lo) {
    __half2 h = __float22half2_rn(v);
    hi = *(uint32_t*)&h;
    float2 hf = __half22float2(h);
    __half2 l = __float22half2_rn(make_float2(v.x - hf.x, v.y - hf.y));
    lo = *(uint32_t*)&l;
}
__device__ __forceinline__ void mma_f16(float* d, const uint32_t* a, uint32_t b0, uint32_t b1) {
    asm volatile(
        "mma.sync.aligned.m16n8k16.row.col.f32.f16.f16.f32 "
        "{%0,%1,%2,%3}, {%4,%5,%6,%7}, {%8,%9}, {%0,%1,%2,%3};"
        : "+f"(d[0]), "+f"(d[1]), "+f"(d[2]), "+f"(d[3])
        : "r"(a[0]), "r"(a[1]), "r"(a[2]), "r"(a[3]), "r"(b0), "r"(b1));
}

// ---------------- prep ----------------
__global__ void k_prep0() {
    int i = blockIdx.x * blockDim.x + threadIdx.x;
    if (i < N_NODES) g_degcnt[i] = 0;
    if (i < L * 2 * C) g_stats[i] = 0.0f;
}
__global__ void k_count(const int* __restrict__ dst) {
    int e = blockIdx.x * blockDim.x + threadIdx.x;
    if (e < N_EDGES) atomicAdd(&g_degcnt[dst[e]], 1);
}
__global__ void k_scan() {
    __shared__ int sp[1024];
    int t = threadIdx.x;
    int base = t * 64;
    int sum = 0;
    #pragma unroll 4
    for (int i = 0; i < 64; i++) sum += g_degcnt[base + i];
    sp[t] = sum;
    __syncthreads();
    for (int o = 1; o < 1024; o <<= 1) {
        int v = (t >= o) ? sp[t - o] : 0;
        __syncthreads();
        sp[t] += v;
        __syncthreads();
    }
    int run = sp[t] - sum;
    for (int i = 0; i < 64; i++) {
        int cnt = g_degcnt[base + i];
        g_off[base + i] = run;
        g_cursor[base + i] = run;
        g_deginv[base + i] = 1.0f / fmaxf((float)cnt, 1.0f);
        run += cnt;
    }
    if (t == 1023) g_off[N_NODES] = run;
}
__global__ void k_scatter(const int* __restrict__ src, const int* __restrict__ dst,
                          const float* __restrict__ ew) {
    int e = blockIdx.x * blockDim.x + threadIdx.x;
    if (e >= N_EDGES) return;
    int p = atomicAdd(&g_cursor[dst[e]], 1);
    g_edge[p] = make_float2(__int_as_float(src[e]), log1pf(ew[e]));
}

// ---------------- prep: weights -> pre-packed fp16 mma fragments (single) ----------
// b0 = {B[k0][n], B[k0+1][n]}, b1 = {B[k0+8][n], B[k0+9][n]}; B[k][n] = W[k*128+n]
__global__ void k_wprep(const float* __restrict__ Ws, const float* __restrict__ Wn) {
    int i = blockIdx.x * blockDim.x + threadIdx.x;   // L*2*4096 = 24576
    if (i >= L * 2 * BPK_PER_CHUNK) return;
    int lane  = i & 31;
    int nt    = (i >> 5) & 15;
    int kstep = (i >> 9) & 7;
    int chunk = (i >> 12) & 1;
    int l     = i >> 13;
    const float* W = (chunk ? Wn : Ws) + (size_t)l * 16384;
    int k0 = kstep * 16 + (lane & 3) * 2;
    int n  = nt * 8 + (lane >> 2);
    uint32_t b0 = pack_f16x2(make_float2(W[(k0 + 0) * 128 + n], W[(k0 + 1) * 128 + n]));
    uint32_t b1 = pack_f16x2(make_float2(W[(k0 + 8) * 128 + n], W[(k0 + 9) * 128 + n]));
    g_Bpk[i] = make_uint2(b0, b1);
}

// ---------------- one-time: BN column stats of x (layer 0) ----------------
__global__ void k_stats(const float* __restrict__ x) {
    int tid = threadIdx.x;
    int c = tid & (C - 1);
    int rr = tid >> 7;
    float s = 0.0f, s2 = 0.0f;
    for (int r = blockIdx.x * 2 + rr; r < N_NODES; r += gridDim.x * 2) {
        float v = x[(size_t)r * C + c];
        s += v; s2 += v * v;
    }
    atomicAdd(&g_stats[c], s);
    atomicAdd(&g_stats[C + c], s2);
}

// ---------------- per-layer: raw mean aggregation + wbar ----------------
__global__ void k_aggr(const float* __restrict__ in) {
    int n = (blockIdx.x * blockDim.x + threadIdx.x) >> 5;
    int lane = threadIdx.x & 31;
    if (n >= N_NODES) return;
    int beg = g_off[n], end = g_off[n + 1];
    const float4* in4 = (const float4*)in;
    float4 a0 = make_float4(0.f, 0.f, 0.f, 0.f);
    float4 a1 = make_float4(0.f, 0.f, 0.f, 0.f);
    float ws = 0.f;
    int i = beg;
    for (; i + 4 <= end; i += 4) {
        float2 e0 = g_edge[i],     e1 = g_edge[i + 1];
        float2 e2 = g_edge[i + 2], e3 = g_edge[i + 3];
        float4 v0 = __ldg(&in4[(size_t)__float_as_int(e0.x) * 32 + lane]);
        float4 v1 = __ldg(&in4[(size_t)__float_as_int(e1.x) * 32 + lane]);
        float4 v2 = __ldg(&in4[(size_t)__float_as_int(e2.x) * 32 + lane]);
        float4 v3 = __ldg(&in4[(size_t)__float_as_int(e3.x) * 32 + lane]);
        a0.x += e0.y * v0.x; a0.y += e0.y * v0.y; a0.z += e0.y * v0.z; a0.w += e0.y * v0.w;
        a1.x += e1.y * v1.x; a1.y += e1.y * v1.y; a1.z += e1.y * v1.z; a1.w += e1.y * v1.w;
        a0.x += e2.y * v2.x; a0.y += e2.y * v2.y; a0.z += e2.y * v2.z; a0.w += e2.y * v2.w;
        a1.x += e3.y * v3.x; a1.y += e3.y * v3.y; a1.z += e3.y * v3.z; a1.w += e3.y * v3.w;
        ws += (e0.y + e1.y) + (e2.y + e3.y);
    }
    for (; i < end; i++) {
        float2 e = g_edge[i];
        float4 v = __ldg(&in4[(size_t)__float_as_int(e.x) * 32 + lane]);
        a0.x += e.y * v.x; a0.y += e.y * v.y; a0.z += e.y * v.z; a0.w += e.y * v.w;
        ws += e.y;
    }
    float di = g_deginv[n];
    float4 acc = make_float4((a0.x + a1.x) * di, (a0.y + a1.y) * di,
                             (a0.z + a1.z) * di, (a0.w + a1.w) * di);
    ((float4*)g_neigh)[(size_t)n * 32 + lane] = acc;
    if (lane == 0) g_wbar[n] = ws * di;
}

// ---------------- per-layer: 2-pass fp16 mma.sync dual GEMM, fused BN ---------------
// A = Ah + Al (fp16 split, ~exact); B = single fp16 (err 2^-12).
// D = (Ah+Al) @ B_f16 : 2 MMAs per fragment (was 3). Warp w owns 16 rows x 128 cols.
// mode 0: write g_h + accumulate next-layer BN stats.  mode 1: fused final dot.
// smem: 32768 (sB one chunk) + 512 + 512 + 1024 = 34816
#define GEMM_SMEM (32768 + 2048)

__global__ __launch_bounds__(256, 2)
void k_gemm(int l, const float* __restrict__ Ain,
            const float* __restrict__ gamma, const float* __restrict__ beta,
            const float* __restrict__ bias,
            const float* __restrict__ lin_w, const float* __restrict__ lin_b,
            float* __restrict__ out, int mode) {
    extern __shared__ unsigned char dyn[];
    uint2* sB    = (uint2*)dyn;                 // 32KB: packed fp16 B fragments
    float* sSc   = (float*)(dyn + 32768);       // 128
    float* sSh   = sSc + 128;                   // 128
    float* sStat = sSh + 128;                   // 256

    int tid = threadIdx.x, wid = tid >> 5, lane = tid & 31;
    int row0 = blockIdx.x * 128;

    // BN affine coefficients (fused k_coef)
    if (tid < 128) {
        float sum = g_stats[l * 2 * C + tid];
        float sq  = g_stats[l * 2 * C + C + tid];
        float mu  = sum * (1.0f / N_NODES);
        float var = sq * (1.0f / N_NODES) - mu * mu;
        float sc  = gamma[l * C + tid] * rsqrtf(var + BN_EPS);
        sSc[tid] = sc;
        sSh[tid] = beta[l * C + tid] - mu * sc;
    }
    if (tid < 256) sStat[tid] = 0.0f;

    float acc[16][4];
    #pragma unroll
    for (int nt = 0; nt < 16; nt++)
        #pragma unroll
        for (int q = 0; q < 4; q++) acc[nt][q] = 0.0f;

    int ar = row0 + wid * 16 + (lane >> 2);   // A fragment base row (this + ar+8)
    int ak = (lane & 3) * 2;
    float wb0 = g_wbar[ar], wb1 = g_wbar[ar + 8];

    #pragma unroll 1
    for (int chunk = 0; chunk < 2; chunk++) {
        if (chunk) __syncthreads();
        {
            const uint4* src = (const uint4*)(g_Bpk + (size_t)(l * 2 + chunk) * BPK_PER_CHUNK);
            uint4* dst = (uint4*)sB;
            #pragma unroll
            for (int it = 0; it < 8; it++) dst[it * 256 + tid] = src[it * 256 + tid];
        }
        __syncthreads();

        const float* Asrc = chunk ? g_neigh : Ain;
        float m0 = chunk ? wb0 : 1.0f;
        float m1 = chunk ? wb1 : 1.0f;

        #pragma unroll 2
        for (int ks = 0; ks < 8; ks++) {
            int kk = ks * 16 + ak;
            float2 scA = *(const float2*)&sSc[kk];
            float2 scB = *(const float2*)&sSc[kk + 8];
            float2 shA = *(const float2*)&sSh[kk];
            float2 shB = *(const float2*)&sSh[kk + 8];

            const float* p = Asrc + (size_t)ar * C + kk;
            float2 v0 = *(const float2*)(p);
            float2 v1 = *(const float2*)(p + 8 * C);
            float2 v2 = *(const float2*)(p + 8);
            float2 v3 = *(const float2*)(p + 8 * C + 8);
            v0.x = v0.x * scA.x + shA.x * m0; v0.y = v0.y * scA.y + shA.y * m0;
            v1.x = v1.x * scA.x + shA.x * m1; v1.y = v1.y * scA.y + shA.y * m1;
            v2.x = v2.x * scB.x + shB.x * m0; v2.y = v2.y * scB.y + shB.y * m0;
            v3.x = v3.x * scB.x + shB.x * m1; v3.y = v3.y * scB.y + shB.y * m1;

            uint32_t ahi[4], alo[4];
            cvt_hilo_f16(v0, ahi[0], alo[0]);
            cvt_hilo_f16(v1, ahi[1], alo[1]);
            cvt_hilo_f16(v2, ahi[2], alo[2]);
            cvt_hilo_f16(v3, ahi[3], alo[3]);

            #pragma unroll
            for (int nt = 0; nt < 16; nt++) {
                uint2 b = sB[(ks * 16 + nt) * 32 + lane];
                mma_f16(acc[nt], ahi, b.x, b.y);
                mma_f16(acc[nt], alo, b.x, b.y);
            }
        }
    }

    if (mode == 0) {
        // epilogue: bias + ReLU, write g_h, accumulate next-layer BN stats
        #pragma unroll
        for (int nt = 0; nt < 16; nt++) {
            int col = nt * 8 + (lane & 3) * 2;
            float b0 = bias[col], b1 = bias[col + 1];
            float o00 = fmaxf(acc[nt][0] + b0, 0.f);
            float o01 = fmaxf(acc[nt][1] + b1, 0.f);
            float o10 = fmaxf(acc[nt][2] + b0, 0.f);
            float o11 = fmaxf(acc[nt][3] + b1, 0.f);
            *(float2*)(g_h + (size_t)ar * C + col)       = make_float2(o00, o01);
            *(float2*)(g_h + (size_t)(ar + 8) * C + col) = make_float2(o10, o11);
            float s0 = o00 + o10, s1 = o01 + o11;
            float q0 = o00 * o00 + o10 * o10, q1 = o01 * o01 + o11 * o11;
            #pragma unroll
            for (int off = 16; off >= 4; off >>= 1) {
                s0 += __shfl_down_sync(0xffffffffu, s0, off);
                s1 += __shfl_down_sync(0xffffffffu, s1, off);
                q0 += __shfl_down_sync(0xffffffffu, q0, off);
                q1 += __shfl_down_sync(0xffffffffu, q1, off);
            }
            if (lane < 4) {
                atomicAdd(&sStat[col],           s0);
                atomicAdd(&sStat[col + 1],       s1);
                atomicAdd(&sStat[128 + col],     q0);
                atomicAdd(&sStat[128 + col + 1], q1);
            }
        }
        __syncthreads();
        if (tid < 128) {
            atomicAdd(&g_stats[(l + 1) * 2 * C + tid],     sStat[tid]);
            atomicAdd(&g_stats[(l + 1) * 2 * C + C + tid], sStat[128 + tid]);
        }
    } else {
        // last layer: fused final dot over this warp's 16 rows
        float p0 = 0.f, p1 = 0.f;
        #pragma unroll
        for (int nt = 0; nt < 16; nt++) {
            int col = nt * 8 + (lane & 3) * 2;
            float b0 = bias[col], b1 = bias[col + 1];
            float lw0 = lin_w[col], lw1 = lin_w[col + 1];
            float o00 = fmaxf(acc[nt][0] + b0, 0.f);
            float o01 = fmaxf(acc[nt][1] + b1, 0.f);
            float o10 = fmaxf(acc[nt][2] + b0, 0.f);
            float o11 = fmaxf(acc[nt][3] + b1, 0.f);
            p0 += o00 * lw0 + o01 * lw1;
            p1 += o10 * lw0 + o11 * lw1;
        }
        p0 += __shfl_xor_sync(0xffffffffu, p0, 1);
        p0 += __shfl_xor_sync(0xffffffffu, p0, 2);
        p1 += __shfl_xor_sync(0xffffffffu, p1, 1);
        p1 += __shfl_xor_sync(0xffffffffu, p1, 2);
        if ((lane & 3) == 0) {
            float lb = lin_b[0];
            out[ar] = p0 + lb;
            out[ar + 8] = p1 + lb;
        }
    }
}

// ---------------- launch ----------------
extern "C" void kernel_launch(void* const* d_in, const int* in_sizes, int n_in,
                              void* d_out, int out_size) {
    const float* x      = (const float*)d_in[0];
    const float* ew     = (const float*)d_in[1];
    const float* gamma  = (const float*)d_in[2];
    const float* beta   = (const float*)d_in[3];
    const float* Wself  = (const float*)d_in[4];
    const float* Wneigh = (const float*)d_in[5];
    const float* bias   = (const float*)d_in[6];
    const float* lin_w  = (const float*)d_in[7];
    const float* lin_b  = (const float*)d_in[8];
    const int*   src    = (const int*)d_in[9];
    const int*   dst    = (const int*)d_in[10];
    float*       out    = (float*)d_out;

    (void)in_sizes; (void)n_in; (void)out_size;

    cudaFuncSetAttribute(k_gemm, cudaFuncAttributeMaxDynamicSharedMemorySize, GEMM_SMEM);

    float* hdev = nullptr;
    cudaGetSymbolAddress((void**)&hdev, g_h);

    k_prep0  <<<N_NODES / 256, 256>>>();
    k_count  <<<N_EDGES / 256, 256>>>(dst);
    k_scan   <<<1, 1024>>>();
    k_scatter<<<N_EDGES / 256, 256>>>(src, dst, ew);
    k_wprep  <<<(L * 2 * BPK_PER_CHUNK) / 256, 256>>>(Wself, Wneigh);
    k_stats  <<<256, 256>>>(x);

    for (int l = 0; l < L; l++) {
        const float* in = (l == 0) ? x : hdev;
        k_aggr<<<N_NODES * 32 / 256, 256>>>(in);
        k_gemm<<<N_NODES / 128, 256, GEMM_SMEM>>>(l, in, gamma, beta,
                                                  bias + (size_t)l * C,
                                                  lin_w, lin_b, out,
                                                  (l == L - 1) ? 1 : 0);
    }
}